// round 3
// baseline (speedup 1.0000x reference)
#include <cuda_runtime.h>
#include <cstdint>
#include <cstddef>

#define NU_N 100000
#define NI_N 100000
#define NEDGE 600000
#define D 128

// ---------------- scratch (static device globals; 16B-aligned; ~154 MB) --------
__device__ __align__(16) float g_Wh[(size_t)NU_N * D];     // reused per etype
__device__ __align__(16) float g_S_iu[(size_t)NU_N * D];
__device__ __align__(16) float g_S_uu[(size_t)NU_N * D];
__device__ __align__(16) float g_deg_ui[NI_N];
__device__ __align__(16) float g_deg_iu[NU_N];
__device__ __align__(16) float g_deg_uu[NU_N];

// ---------------- GEMM: out[n,128] = A[n,128] @ W[128,128] + b ----------------
// 256 threads, 64 rows per CTA. Static smem only: A tile 32KB + W k-chunk 16KB.
// Warp handles 8 rows x 128 cols; lane j owns cols 4j..4j+3.
#define RPC 64

__global__ void __launch_bounds__(256)
gemm128(const float* __restrict__ A, const float* __restrict__ W,
        const float* __restrict__ bias, float* __restrict__ out, int n) {
    __shared__ float As[RPC][128];   // 32 KB, row-major (reads are broadcast)
    __shared__ float Ws[32][128];    // 16 KB, one k-chunk of W

    int tid = threadIdx.x;
    int rowBase = blockIdx.x * RPC;

    // load A tile: 64 rows * 32 float4 = 2048 float4, 8 per thread, coalesced
    const float4* A4 = (const float4*)A;
    float4* As4 = (float4*)&As[0][0];
#pragma unroll
    for (int it = 0; it < 8; ++it) {
        int idx = tid + it * 256;
        int r = idx >> 5, c4 = idx & 31;
        int ar = rowBase + r;
        if (ar >= n) ar = n - 1;            // clamp (stores are guarded)
        As4[idx] = A4[(size_t)ar * 32 + c4];
    }

    int warp = tid >> 5, lane = tid & 31;
    int wrow = warp * 8;

    float4 b4 = ((const float4*)bias)[lane];
    float acc[8][4];
#pragma unroll
    for (int r = 0; r < 8; ++r) {
        acc[r][0] = b4.x; acc[r][1] = b4.y; acc[r][2] = b4.z; acc[r][3] = b4.w;
    }

#pragma unroll 1
    for (int kc = 0; kc < 4; ++kc) {
        __syncthreads();                    // As ready (kc=0) / prev Ws drained
        // load W rows [kc*32, kc*32+32): 1024 float4, 4 per thread
        const float4* Wc4 = (const float4*)(W + (size_t)kc * 32 * 128);
        float4* Ws4 = (float4*)&Ws[0][0];
#pragma unroll
        for (int it = 0; it < 4; ++it) Ws4[tid + it * 256] = Wc4[tid + it * 256];
        __syncthreads();

#pragma unroll
        for (int kk = 0; kk < 32; ++kk) {
            float4 w4 = ((const float4*)&Ws[kk][0])[lane];   // LDS.128 conflict-free
            int k = kc * 32 + kk;
#pragma unroll
            for (int r = 0; r < 8; ++r) {
                float a = As[wrow + r][k];                   // broadcast LDS
                acc[r][0] += a * w4.x;
                acc[r][1] += a * w4.y;
                acc[r][2] += a * w4.z;
                acc[r][3] += a * w4.w;
            }
        }
    }

#pragma unroll
    for (int r = 0; r < 8; ++r) {
        int gr = rowBase + wrow + r;
        if (gr < n)
            ((float4*)(out + (size_t)gr * D))[lane] =
                make_float4(acc[r][0], acc[r][1], acc[r][2], acc[r][3]);
    }
}

// ---------------- edge scatter: warp per edge, vector reduction ----------------
__global__ void __launch_bounds__(256)
scatter_mean(const float* __restrict__ Wh, const int* __restrict__ src,
             const int* __restrict__ dst, float* __restrict__ S,
             float* __restrict__ deg) {
    int g = blockIdx.x * blockDim.x + threadIdx.x;
    int e = g >> 5;
    int lane = g & 31;
    if (e >= NEDGE) return;
    int s = __ldg(src + e);
    int d = __ldg(dst + e);
    float4 v = ((const float4*)(Wh + (size_t)s * D))[lane];   // coalesced gather
    float* p = S + (size_t)d * D + lane * 4;
    asm volatile("red.global.add.v4.f32 [%0], {%1, %2, %3, %4};"
                 :: "l"(p), "f"(v.x), "f"(v.y), "f"(v.z), "f"(v.w)
                 : "memory");
    if (lane == 0) atomicAdd(deg + d, 1.0f);
}

// ---------------- finalize: mean + sum of etypes ----------------
__global__ void __launch_bounds__(256)
finalize_out(float* __restrict__ out,              // [2, N, 128]: user then item
             const float* __restrict__ S_iu, const float* __restrict__ S_uu,
             const float* __restrict__ deg_ui, const float* __restrict__ deg_iu,
             const float* __restrict__ deg_uu) {
    int idx = blockIdx.x * blockDim.x + threadIdx.x;   // float4 index over N*32
    if (idx >= NU_N * 32) return;
    int node = idx >> 5;
    float dui = deg_ui[node], diu = deg_iu[node], duu = deg_uu[node];
    float rui = dui > 0.f ? 1.f / dui : 0.f;
    float riu = diu > 0.f ? 1.f / diu : 0.f;
    float ruu = duu > 0.f ? 1.f / duu : 0.f;

    float4 a = ((const float4*)S_iu)[idx];
    float4 b = ((const float4*)S_uu)[idx];
    ((float4*)out)[idx] = make_float4(a.x * riu + b.x * ruu, a.y * riu + b.y * ruu,
                                      a.z * riu + b.z * ruu, a.w * riu + b.w * ruu);

    float4* itemOut = (float4*)(out + (size_t)NU_N * D);
    float4 c = itemOut[idx];   // holds raw ui sums
    itemOut[idx] = make_float4(c.x * rui, c.y * rui, c.z * rui, c.w * rui);
}

// ---------------- launch ----------------
extern "C" void kernel_launch(void* const* d_in, const int* in_sizes, int n_in,
                              void* d_out, int out_size) {
    const float* feat_user = (const float*)d_in[0];
    const float* feat_item = (const float*)d_in[1];
    const float* W_ui = (const float*)d_in[2];
    const float* b_ui = (const float*)d_in[3];
    const float* W_iu = (const float*)d_in[4];
    const float* b_iu = (const float*)d_in[5];
    const float* W_uu = (const float*)d_in[6];
    const float* b_uu = (const float*)d_in[7];
    const int* src_ui = (const int*)d_in[8];
    const int* dst_ui = (const int*)d_in[9];
    const int* src_iu = (const int*)d_in[10];
    const int* dst_iu = (const int*)d_in[11];
    const int* src_uu = (const int*)d_in[12];
    const int* dst_uu = (const int*)d_in[13];
    float* out = (float*)d_out;

    void *pWh, *pS_iu, *pS_uu, *pd_ui, *pd_iu, *pd_uu;
    cudaGetSymbolAddress(&pWh, g_Wh);
    cudaGetSymbolAddress(&pS_iu, g_S_iu);
    cudaGetSymbolAddress(&pS_uu, g_S_uu);
    cudaGetSymbolAddress(&pd_ui, g_deg_ui);
    cudaGetSymbolAddress(&pd_iu, g_deg_iu);
    cudaGetSymbolAddress(&pd_uu, g_deg_uu);

    // zero accumulators (d_out item half doubles as the ui sum accumulator)
    cudaMemsetAsync(out, 0, (size_t)2 * NU_N * D * sizeof(float));
    cudaMemsetAsync(pS_iu, 0, (size_t)NU_N * D * sizeof(float));
    cudaMemsetAsync(pS_uu, 0, (size_t)NU_N * D * sizeof(float));
    cudaMemsetAsync(pd_ui, 0, NI_N * sizeof(float));
    cudaMemsetAsync(pd_iu, 0, NU_N * sizeof(float));
    cudaMemsetAsync(pd_uu, 0, NU_N * sizeof(float));

    int gGrid = (NU_N + RPC - 1) / RPC;
    int sBlocks = (NEDGE * 32 + 255) / 256;

    // etype ui: user -> item (sums straight into out item half)
    gemm128<<<gGrid, 256>>>(feat_user, W_ui, b_ui, (float*)pWh, NU_N);
    scatter_mean<<<sBlocks, 256>>>((const float*)pWh, src_ui, dst_ui,
                                   out + (size_t)NU_N * D, (float*)pd_ui);
    // etype iu: item -> user
    gemm128<<<gGrid, 256>>>(feat_item, W_iu, b_iu, (float*)pWh, NI_N);
    scatter_mean<<<sBlocks, 256>>>((const float*)pWh, src_iu, dst_iu,
                                   (float*)pS_iu, (float*)pd_iu);
    // etype uu: user -> user
    gemm128<<<gGrid, 256>>>(feat_user, W_uu, b_uu, (float*)pWh, NU_N);
    scatter_mean<<<sBlocks, 256>>>((const float*)pWh, src_uu, dst_uu,
                                   (float*)pS_uu, (float*)pd_uu);

    // finalize means + sum
    finalize_out<<<(NU_N * 32 + 255) / 256, 256>>>(
        out, (const float*)pS_iu, (const float*)pS_uu,
        (const float*)pd_ui, (const float*)pd_iu, (const float*)pd_uu);
}

// round 4
// speedup vs baseline: 1.4107x; 1.4107x over previous
#include <cuda_runtime.h>
#include <cstdint>
#include <cstddef>

#define NU_N 100000
#define NI_N 100000
#define NN 100000          // all node sets are the same size
#define NEDGE 600000
#define D 128
#define NBLK 98            // ceil(NN / 1024)

// ---------------- scratch (static device globals; 16B-aligned) ----------------
__device__ __align__(16) float g_WhA[(size_t)NN * D];
__device__ __align__(16) float g_WhB[(size_t)NN * D];
__device__ __align__(16) int g_deg[3 * NN];          // per-etype dst degree
__device__ __align__(16) int g_off[3 * (NN + 1)];    // CSR offsets
__device__ __align__(16) int g_bsum[3 * 128];        // scan block sums
__device__ __align__(16) int g_cur[3 * NN];          // fill cursors
__device__ __align__(16) int g_esrc[3 * NEDGE];      // CSR: src ids grouped by dst

// ---------------- GEMM: out[n,128] = A[n,128] @ W[128,128] + b ----------------
#define RPC 64

__global__ void __launch_bounds__(256)
gemm128(const float* __restrict__ A, const float* __restrict__ W,
        const float* __restrict__ bias, float* __restrict__ out, int n) {
    __shared__ float As[RPC][128];
    __shared__ float Ws[32][128];

    int tid = threadIdx.x;
    int rowBase = blockIdx.x * RPC;

    const float4* A4 = (const float4*)A;
    float4* As4 = (float4*)&As[0][0];
#pragma unroll
    for (int it = 0; it < 8; ++it) {
        int idx = tid + it * 256;
        int r = idx >> 5, c4 = idx & 31;
        int ar = rowBase + r;
        if (ar >= n) ar = n - 1;
        As4[idx] = A4[(size_t)ar * 32 + c4];
    }

    int warp = tid >> 5, lane = tid & 31;
    int wrow = warp * 8;

    float4 b4 = ((const float4*)bias)[lane];
    float acc[8][4];
#pragma unroll
    for (int r = 0; r < 8; ++r) {
        acc[r][0] = b4.x; acc[r][1] = b4.y; acc[r][2] = b4.z; acc[r][3] = b4.w;
    }

#pragma unroll 1
    for (int kc = 0; kc < 4; ++kc) {
        __syncthreads();
        const float4* Wc4 = (const float4*)(W + (size_t)kc * 32 * 128);
        float4* Ws4 = (float4*)&Ws[0][0];
#pragma unroll
        for (int it = 0; it < 4; ++it) Ws4[tid + it * 256] = Wc4[tid + it * 256];
        __syncthreads();

#pragma unroll
        for (int kk = 0; kk < 32; ++kk) {
            float4 w4 = ((const float4*)&Ws[kk][0])[lane];
            int k = kc * 32 + kk;
#pragma unroll
            for (int r = 0; r < 8; ++r) {
                float a = As[wrow + r][k];
                acc[r][0] += a * w4.x;
                acc[r][1] += a * w4.y;
                acc[r][2] += a * w4.z;
                acc[r][3] += a * w4.w;
            }
        }
    }

#pragma unroll
    for (int r = 0; r < 8; ++r) {
        int gr = rowBase + wrow + r;
        if (gr < n)
            ((float4*)(out + (size_t)gr * D))[lane] =
                make_float4(acc[r][0], acc[r][1], acc[r][2], acc[r][3]);
    }
}

// ---------------- CSR build ----------------
// histogram of dst degrees, 3 etypes via blockIdx.y
__global__ void __launch_bounds__(256)
hist3(const int* __restrict__ d0, const int* __restrict__ d1,
      const int* __restrict__ d2, int* __restrict__ deg) {
    int e = blockIdx.x * 256 + threadIdx.x;
    if (e >= NEDGE) return;
    int y = blockIdx.y;
    const int* d = (y == 0) ? d0 : (y == 1) ? d1 : d2;
    atomicAdd(deg + y * NN + __ldg(d + e), 1);
}

// block-local exclusive scan (1024 elems/block), records block totals
__global__ void __launch_bounds__(256)
scan1(const int* __restrict__ deg, int* __restrict__ off, int* __restrict__ bsum) {
    int y = blockIdx.y;
    const int* d = deg + y * NN;
    int* o = off + y * (NN + 1);
    int tid = threadIdx.x, lane = tid & 31, warp = tid >> 5;
    int base = blockIdx.x * 1024 + tid * 4;

    int v0 = (base + 0 < NN) ? d[base + 0] : 0;
    int v1 = (base + 1 < NN) ? d[base + 1] : 0;
    int v2 = (base + 2 < NN) ? d[base + 2] : 0;
    int v3 = (base + 3 < NN) ? d[base + 3] : 0;
    int tsum = v0 + v1 + v2 + v3;

    int x = tsum;
#pragma unroll
    for (int ofs = 1; ofs < 32; ofs <<= 1) {
        int t = __shfl_up_sync(0xffffffffu, x, ofs);
        if (lane >= ofs) x += t;
    }
    __shared__ int ws[8];
    if (lane == 31) ws[warp] = x;
    __syncthreads();
    if (tid == 0) {
        int run = 0;
#pragma unroll
        for (int i = 0; i < 8; ++i) { int t = ws[i]; ws[i] = run; run += t; }
        bsum[y * 128 + blockIdx.x] = run;
    }
    __syncthreads();

    int excl = ws[warp] + x - tsum;
    if (base + 0 < NN) o[base + 0] = excl;
    if (base + 1 < NN) o[base + 1] = excl + v0;
    if (base + 2 < NN) o[base + 2] = excl + v0 + v1;
    if (base + 3 < NN) o[base + 3] = excl + v0 + v1 + v2;
}

// exclusive scan of block sums (98 entries; serial by one thread, tiny)
__global__ void __launch_bounds__(32)
scan2(int* __restrict__ bsum) {
    if (threadIdx.x == 0) {
        int* b = bsum + blockIdx.y * 128;
        int run = 0;
        for (int i = 0; i < NBLK; ++i) { int t = b[i]; b[i] = run; run += t; }
    }
}

// add block offsets; copy to cursor; set off[NN]
__global__ void __launch_bounds__(256)
scan3(int* __restrict__ off, const int* __restrict__ bsum, int* __restrict__ cur) {
    int y = blockIdx.y;
    int* o = off + y * (NN + 1);
    int* c = cur + y * NN;
    int add = bsum[y * 128 + blockIdx.x];
    int base = blockIdx.x * 1024 + threadIdx.x * 4;
#pragma unroll
    for (int i = 0; i < 4; ++i) {
        int idx = base + i;
        if (idx < NN) { int v = o[idx] + add; o[idx] = v; c[idx] = v; }
    }
    if (blockIdx.x == 0 && threadIdx.x == 0) o[NN] = NEDGE;
}

// scatter edge src ids into CSR slots
__global__ void __launch_bounds__(256)
fill3(const int* __restrict__ s0, const int* __restrict__ d0,
      const int* __restrict__ s1, const int* __restrict__ d1,
      const int* __restrict__ s2, const int* __restrict__ d2,
      int* __restrict__ cur, int* __restrict__ esrc) {
    int e = blockIdx.x * 256 + threadIdx.x;
    if (e >= NEDGE) return;
    int y = blockIdx.y;
    const int* s = (y == 0) ? s0 : (y == 1) ? s1 : s2;
    const int* d = (y == 0) ? d0 : (y == 1) ? d1 : d2;
    int dn = __ldg(d + e);
    int pos = atomicAdd(cur + y * NN + dn, 1);
    esrc[y * NEDGE + pos] = __ldg(s + e);
}

// ---------------- pull aggregation ----------------
__device__ __forceinline__ void acc4(float4& acc, const float4& a) {
    acc.x += a.x; acc.y += a.y; acc.z += a.z; acc.w += a.w;
}

__device__ __forceinline__ float4 pull_seg(const float* __restrict__ Wh,
                                           const int* __restrict__ esrc,
                                           int s0, int s1, int lane) {
    float4 acc = make_float4(0.f, 0.f, 0.f, 0.f);
    int e = s0;
    for (; e + 4 <= s1; e += 4) {
        int i0 = __ldg(esrc + e + 0);
        int i1 = __ldg(esrc + e + 1);
        int i2 = __ldg(esrc + e + 2);
        int i3 = __ldg(esrc + e + 3);
        float4 a = ((const float4*)(Wh + (size_t)i0 * D))[lane];
        float4 b = ((const float4*)(Wh + (size_t)i1 * D))[lane];
        float4 c = ((const float4*)(Wh + (size_t)i2 * D))[lane];
        float4 dd = ((const float4*)(Wh + (size_t)i3 * D))[lane];
        acc4(acc, a); acc4(acc, b); acc4(acc, c); acc4(acc, dd);
    }
    for (; e < s1; ++e) {
        int i = __ldg(esrc + e);
        float4 a = ((const float4*)(Wh + (size_t)i * D))[lane];
        acc4(acc, a);
    }
    return acc;
}

// item output: mean over ui edges
__global__ void __launch_bounds__(256)
pull_item(const float* __restrict__ Wh, const int* __restrict__ off,
          const int* __restrict__ esrc, float* __restrict__ out) {
    int g = blockIdx.x * 256 + threadIdx.x;
    int node = g >> 5, lane = g & 31;
    if (node >= NN) return;
    int s0 = __ldg(off + node), s1 = __ldg(off + node + 1);
    float4 acc = pull_seg(Wh, esrc, s0, s1, lane);
    float r = (s1 > s0) ? 1.f / (float)(s1 - s0) : 0.f;
    ((float4*)(out + (size_t)node * D))[lane] =
        make_float4(acc.x * r, acc.y * r, acc.z * r, acc.w * r);
}

// user output: mean(iu) + mean(uu)
__global__ void __launch_bounds__(256)
pull_user(const float* __restrict__ WhIU, const int* __restrict__ offIU,
          const int* __restrict__ esrcIU,
          const float* __restrict__ WhUU, const int* __restrict__ offUU,
          const int* __restrict__ esrcUU, float* __restrict__ out) {
    int g = blockIdx.x * 256 + threadIdx.x;
    int node = g >> 5, lane = g & 31;
    if (node >= NN) return;
    int a0 = __ldg(offIU + node), a1 = __ldg(offIU + node + 1);
    int b0 = __ldg(offUU + node), b1 = __ldg(offUU + node + 1);
    float4 ai = pull_seg(WhIU, esrcIU, a0, a1, lane);
    float4 au = pull_seg(WhUU, esrcUU, b0, b1, lane);
    float ri = (a1 > a0) ? 1.f / (float)(a1 - a0) : 0.f;
    float ru = (b1 > b0) ? 1.f / (float)(b1 - b0) : 0.f;
    ((float4*)(out + (size_t)node * D))[lane] =
        make_float4(ai.x * ri + au.x * ru, ai.y * ri + au.y * ru,
                    ai.z * ri + au.z * ru, ai.w * ri + au.w * ru);
}

// ---------------- launch ----------------
extern "C" void kernel_launch(void* const* d_in, const int* in_sizes, int n_in,
                              void* d_out, int out_size) {
    const float* feat_user = (const float*)d_in[0];
    const float* feat_item = (const float*)d_in[1];
    const float* W_ui = (const float*)d_in[2];
    const float* b_ui = (const float*)d_in[3];
    const float* W_iu = (const float*)d_in[4];
    const float* b_iu = (const float*)d_in[5];
    const float* W_uu = (const float*)d_in[6];
    const float* b_uu = (const float*)d_in[7];
    const int* src_ui = (const int*)d_in[8];
    const int* dst_ui = (const int*)d_in[9];
    const int* src_iu = (const int*)d_in[10];
    const int* dst_iu = (const int*)d_in[11];
    const int* src_uu = (const int*)d_in[12];
    const int* dst_uu = (const int*)d_in[13];
    float* out = (float*)d_out;

    void *pWhA, *pWhB, *pDeg, *pOff, *pBsum, *pCur, *pEsrc;
    cudaGetSymbolAddress(&pWhA, g_WhA);
    cudaGetSymbolAddress(&pWhB, g_WhB);
    cudaGetSymbolAddress(&pDeg, g_deg);
    cudaGetSymbolAddress(&pOff, g_off);
    cudaGetSymbolAddress(&pBsum, g_bsum);
    cudaGetSymbolAddress(&pCur, g_cur);
    cudaGetSymbolAddress(&pEsrc, g_esrc);

    float* WhA = (float*)pWhA;
    float* WhB = (float*)pWhB;
    int* deg = (int*)pDeg;
    int* off = (int*)pOff;
    int* bsum = (int*)pBsum;
    int* cur = (int*)pCur;
    int* esrc = (int*)pEsrc;

    // ---- CSR build (etype order in arrays: 0=ui, 1=iu, 2=uu) ----
    cudaMemsetAsync(deg, 0, 3 * NN * sizeof(int));
    dim3 eGrid((NEDGE + 255) / 256, 3);
    hist3<<<eGrid, 256>>>(dst_ui, dst_iu, dst_uu, deg);
    dim3 sGrid(NBLK, 3);
    scan1<<<sGrid, 256>>>(deg, off, bsum);
    scan2<<<dim3(1, 3), 32>>>(bsum);
    scan3<<<sGrid, 256>>>(off, bsum, cur);
    fill3<<<eGrid, 256>>>(src_ui, dst_ui, src_iu, dst_iu, src_uu, dst_uu,
                          cur, esrc);

    int gGrid = (NN + RPC - 1) / RPC;
    int pGrid = (NN * 32 + 255) / 256;

    // etype ui: project users, pull into item output half
    gemm128<<<gGrid, 256>>>(feat_user, W_ui, b_ui, WhA, NU_N);
    pull_item<<<pGrid, 256>>>(WhA, off + 0 * (NN + 1), esrc + 0 * NEDGE,
                              out + (size_t)NU_N * D);

    // etypes iu + uu: project, pull into user output half
    gemm128<<<gGrid, 256>>>(feat_item, W_iu, b_iu, WhB, NI_N);
    gemm128<<<gGrid, 256>>>(feat_user, W_uu, b_uu, WhA, NU_N);
    pull_user<<<pGrid, 256>>>(WhB, off + 1 * (NN + 1), esrc + 1 * NEDGE,
                              WhA, off + 2 * (NN + 1), esrc + 2 * NEDGE,
                              out);
}